// round 2
// baseline (speedup 1.0000x reference)
#include <cuda_runtime.h>
#include <math.h>

#define HID 512
#define BAT 64
#define SEQ 1024
#define INS 256
#define OUTS 256
#define WROW 768   // INS + HID

// scan partition: 128 CTAs = 16 row-groups x 8 batch-groups
#define NRG 16
#define RPC 32     // rows per CTA
#define BPC 8      // batches per CTA
#define NCTA 128
#define KCH 8      // k-chunks (warps) per CTA
#define KLEN 64    // k elements per chunk

// ---------------- static device scratch (no allocations) --------------------
__device__ float g_xp[(size_t)SEQ * BAT * HID];    // x_proj  [s][b][h]
__device__ float g_hseq[(size_t)BAT * SEQ * HID];  // hidden  [b][s][h]
__device__ float g_h[2][HID * BAT];                // h ping-pong [k][b]
__device__ unsigned g_bar;

// ---------------- f32x2 helpers ---------------------------------------------
__device__ __forceinline__ unsigned long long f2dup(float a) {
    unsigned long long r;
    asm("mov.b64 %0, {%1, %1};" : "=l"(r) : "f"(a));
    return r;
}
__device__ __forceinline__ void ffma2(unsigned long long& d,
                                      unsigned long long a,
                                      unsigned long long b) {
    asm("fma.rn.f32x2 %0, %1, %2, %0;" : "+l"(d) : "l"(a), "l"(b));
}
__device__ __forceinline__ float2 unpk(unsigned long long a) {
    float2 f;
    asm("mov.b64 {%0, %1}, %2;" : "=f"(f.x), "=f"(f.y) : "l"(a));
    return f;
}

// ---------------- init: zero barrier + h ping-pong ---------------------------
__global__ void k_init() {
    int tid = blockIdx.x * blockDim.x + threadIdx.x;
    if (tid == 0) g_bar = 0u;
    int n = 2 * HID * BAT;
    float* p = &g_h[0][0];
    for (int i = tid; i < n; i += gridDim.x * blockDim.x) p[i] = 0.0f;
}

// ---------------- GEMM: xp[s][b][h] = sum_i Wx[h][i]*x[b][s][i] + b_ih[h] ---
#define GKC 32
__global__ void __launch_bounds__(256) k_gemm(const float* __restrict__ x,
                                              const float* __restrict__ W,
                                              const float* __restrict__ bih) {
    __shared__ float wxs[GKC][132];  // [k][h within 128-tile]
    __shared__ float xs[GKC][68];    // [k][b]
    const int s  = blockIdx.y;
    const int h0 = blockIdx.x * 128;
    const int tid = threadIdx.x;
    const int bg = tid & 7;    // batch group (8 batches)
    const int hg = tid >> 3;   // h group (4 rows)

    float acc[4][8];
#pragma unroll
    for (int i = 0; i < 4; i++)
#pragma unroll
        for (int j = 0; j < 8; j++) acc[i][j] = 0.0f;

    for (int c = 0; c < INS; c += GKC) {
        {   // W chunk -> wxs[k][h] (transposed)
            int hh = tid >> 1;
            int kk = (tid & 1) * 16;
            const float* src = W + (size_t)(h0 + hh) * WROW + c + kk;
#pragma unroll
            for (int q = 0; q < 4; q++) {
                float4 v = *(const float4*)(src + q * 4);
                wxs[kk + q * 4 + 0][hh] = v.x;
                wxs[kk + q * 4 + 1][hh] = v.y;
                wxs[kk + q * 4 + 2][hh] = v.z;
                wxs[kk + q * 4 + 3][hh] = v.w;
            }
        }
        {   // x chunk -> xs[k][b] (transposed)
            int bb = tid >> 2;
            int kk = (tid & 3) * 8;
            const float* src = x + ((size_t)bb * SEQ + s) * INS + c + kk;
            float4 a = *(const float4*)(src);
            float4 b4 = *(const float4*)(src + 4);
            xs[kk + 0][bb] = a.x;  xs[kk + 1][bb] = a.y;
            xs[kk + 2][bb] = a.z;  xs[kk + 3][bb] = a.w;
            xs[kk + 4][bb] = b4.x; xs[kk + 5][bb] = b4.y;
            xs[kk + 6][bb] = b4.z; xs[kk + 7][bb] = b4.w;
        }
        __syncthreads();
#pragma unroll 4
        for (int k = 0; k < GKC; k++) {
            float4 w4 = *(const float4*)&wxs[k][hg * 4];
            float xv[8];
            *(float4*)&xv[0] = *(const float4*)&xs[k][bg * 8];
            *(float4*)&xv[4] = *(const float4*)&xs[k][bg * 8 + 4];
            float wr[4] = {w4.x, w4.y, w4.z, w4.w};
#pragma unroll
            for (int i = 0; i < 4; i++)
#pragma unroll
                for (int j = 0; j < 8; j++) acc[i][j] += wr[i] * xv[j];
        }
        __syncthreads();
    }
    // epilogue: +bias, store xp[s][b][h] (h fastest)
    float bi[4];
#pragma unroll
    for (int i = 0; i < 4; i++) bi[i] = bih[h0 + hg * 4 + i];
#pragma unroll
    for (int j = 0; j < 8; j++) {
        int b = bg * 8 + j;
        float* dst = g_xp + ((size_t)s * BAT + b) * HID + h0 + hg * 4;
        *(float4*)dst = make_float4(acc[0][j] + bi[0], acc[1][j] + bi[1],
                                    acc[2][j] + bi[2], acc[3][j] + bi[3]);
    }
}

// ---------------- persistent RNN scan ---------------------------------------
__global__ void __launch_bounds__(256) k_scan(const float* __restrict__ W) {
    __shared__ __align__(16) float h_s[HID][BPC];  // 16 KB, [k][b]
    __shared__ float red[KCH * RPC * 9];           // 9 KB

    const int tid = threadIdx.x;
    const int rg = blockIdx.x & (NRG - 1);
    const int bg = blockIdx.x >> 4;
    const int h0 = rg * RPC;
    const int b0 = bg * BPC;
    const int kc = tid >> 5;   // warp = k-chunk
    const int r  = tid & 31;   // row in tile

    // Wh slice in registers: Wh[h0+r][kc*64 .. +63]
    float w[KLEN];
    {
        const float4* wp =
            (const float4*)(W + (size_t)(h0 + r) * WROW + INS + kc * KLEN);
#pragma unroll
        for (int q = 0; q < 16; q++) {
            float4 v = wp[q];
            w[4 * q + 0] = v.x; w[4 * q + 1] = v.y;
            w[4 * q + 2] = v.z; w[4 * q + 3] = v.w;
        }
    }

    // output role: thread (orr = row, ob = batch)
    const int orr = tid & 31;
    const int ob  = tid >> 5;
    const float* xpp = g_xp + (size_t)(b0 + ob) * HID + (h0 + orr);
    float* hseqp = g_hseq + ((size_t)(b0 + ob) * SEQ) * HID + (h0 + orr);

    unsigned tgt = 0;
    for (int t = 0; t < SEQ; t++) {
        float xpv = __ldg(xpp + (size_t)t * BAT * HID);

        // load h_{t-1}[0..511][b0..b0+7] -> smem
        const float* gh = g_h[t & 1];
#pragma unroll
        for (int j = 0; j < 4; j++) {
            int c16 = tid + 256 * j;       // 16-byte chunk id (0..1023)
            int k  = c16 >> 1;
            int bo = (c16 & 1) * 4;
            float4 v = *(const float4*)(gh + (size_t)k * BAT + b0 + bo);
            *(float4*)(&h_s[k][bo]) = v;
        }
        __syncthreads();

        // partial matvec over this warp's k-chunk, 8 batches, f32x2
        unsigned long long a0 = 0ull, a1 = 0ull, a2 = 0ull, a3 = 0ull;
        const float* hbase = &h_s[kc * KLEN][0];
#pragma unroll
        for (int j = 0; j < KLEN; j++) {
            ulonglong2 hA = *(const ulonglong2*)(hbase + 8 * j);
            ulonglong2 hB = *(const ulonglong2*)(hbase + 8 * j + 4);
            unsigned long long w2 = f2dup(w[j]);
            ffma2(a0, w2, hA.x);
            ffma2(a1, w2, hA.y);
            ffma2(a2, w2, hB.x);
            ffma2(a3, w2, hB.y);
        }
        {
            float2 f0 = unpk(a0), f1 = unpk(a1), f2v = unpk(a2), f3 = unpk(a3);
            float* rp = &red[(kc * RPC + r) * 9];
            rp[0] = f0.x;  rp[1] = f0.y;  rp[2] = f1.x;  rp[3] = f1.y;
            rp[4] = f2v.x; rp[5] = f2v.y; rp[6] = f3.x;  rp[7] = f3.y;
        }
        __syncthreads();

        // reduce 8 k-chunks, tanh, publish
        float sum = xpv;
#pragma unroll
        for (int c = 0; c < KCH; c++) sum += red[(c * RPC + orr) * 9 + ob];
        float hv = tanhf(sum);
        g_h[(t + 1) & 1][(size_t)(h0 + orr) * BAT + b0 + ob] = hv;
        hseqp[(size_t)t * HID] = hv;

        // grid-wide release/acquire barrier
        __syncthreads();
        tgt += NCTA;
        if (tid == 0) {
            __threadfence();
            atomicAdd(&g_bar, 1u);
            unsigned v;
            do {
                asm volatile("ld.acquire.gpu.u32 %0, [%1];"
                             : "=r"(v) : "l"(&g_bar) : "memory");
            } while (v < tgt);
        }
        __syncthreads();
    }
}

// ---------------- attention + output projection (CTA per batch) -------------
__global__ void __launch_bounds__(256) k_attn(const float* __restrict__ Who,
                                              const float* __restrict__ bho,
                                              float* __restrict__ out) {
    __shared__ float fin[HID];
    __shared__ float sc[SEQ];
    __shared__ float rbuf[256];
    __shared__ float ctx[HID];

    const int b = blockIdx.x;
    const int tid = threadIdx.x;
    const int lane = tid & 31;
    const int wid = tid >> 5;
    const float* hb = g_hseq + (size_t)b * SEQ * HID;

    for (int i = tid; i < HID; i += 256) fin[i] = hb[(size_t)(SEQ - 1) * HID + i];
    __syncthreads();

    // scores: one warp per seq row
    for (int s = wid; s < SEQ; s += 8) {
        const float* row = hb + (size_t)s * HID;
        float p = 0.0f;
        for (int hh = lane; hh < HID; hh += 32) p += row[hh] * fin[hh];
#pragma unroll
        for (int off = 16; off > 0; off >>= 1)
            p += __shfl_down_sync(0xffffffffu, p, off);
        if (lane == 0) sc[s] = p;
    }
    __syncthreads();

    // softmax over seq
    float m = -1e30f;
    for (int s = tid; s < SEQ; s += 256) m = fmaxf(m, sc[s]);
    rbuf[tid] = m;
    __syncthreads();
    for (int off = 128; off > 0; off >>= 1) {
        if (tid < off) rbuf[tid] = fmaxf(rbuf[tid], rbuf[tid + off]);
        __syncthreads();
    }
    float mx = rbuf[0];
    __syncthreads();
    float ssum = 0.0f;
    for (int s = tid; s < SEQ; s += 256) {
        float e = expf(sc[s] - mx);
        sc[s] = e;
        ssum += e;
    }
    rbuf[tid] = ssum;
    __syncthreads();
    for (int off = 128; off > 0; off >>= 1) {
        if (tid < off) rbuf[tid] += rbuf[tid + off];
        __syncthreads();
    }
    float inv = 1.0f / rbuf[0];
    __syncthreads();
    for (int s = tid; s < SEQ; s += 256) sc[s] *= inv;
    __syncthreads();

    // context: each thread owns 2 h
    {
        float acc0 = 0.0f, acc1 = 0.0f;
        const float* base = hb + 2 * tid;
#pragma unroll 4
        for (int s = 0; s < SEQ; s++) {
            float a = sc[s];
            float2 v = *(const float2*)(base + (size_t)s * HID);
            acc0 += a * v.x;
            acc1 += a * v.y;
        }
        ctx[2 * tid] = acc0;
        ctx[2 * tid + 1] = acc1;
    }
    __syncthreads();

    // out[b][o] = ctx . Who[o] + bho[o]
    {
        int o = tid;
        float acc = bho[o];
        const float4* wp = (const float4*)(Who + (size_t)o * HID);
#pragma unroll 4
        for (int q = 0; q < HID / 4; q++) {
            float4 wv = wp[q];
            const float* cp = &ctx[q * 4];
            acc += wv.x * cp[0] + wv.y * cp[1] + wv.z * cp[2] + wv.w * cp[3];
        }
        out[(size_t)b * OUTS + o] = acc;
    }
}

// ---------------- launch -----------------------------------------------------
extern "C" void kernel_launch(void* const* d_in, const int* in_sizes, int n_in,
                              void* d_out, int out_size) {
    (void)in_sizes; (void)n_in; (void)out_size;
    const float* x    = (const float*)d_in[0];
    const float* W_ih = (const float*)d_in[1];
    const float* b_ih = (const float*)d_in[2];
    const float* W_ho = (const float*)d_in[3];
    const float* b_ho = (const float*)d_in[4];
    float* out = (float*)d_out;

    k_init<<<256, 256>>>();
    k_gemm<<<dim3(4, SEQ), 256>>>(x, W_ih, b_ih);
    k_scan<<<NCTA, 256>>>(W_ih);
    k_attn<<<BAT, 256>>>(W_ho, b_ho, out);
}